// round 1
// baseline (speedup 1.0000x reference)
#include <cuda_runtime.h>
#include <cuda_bf16.h>
#include <math_constants.h>

#define N_NODES 50000
#define E_EDGES 800000
#define IN_DIM  256
#define NH      4
#define ND      32
#define HD      128
#define NEG_SLOPE 0.2f

// ---------------- scratch (device globals; no runtime allocation) -------------
__device__ float g_ft[N_NODES * HD];       // 25.6 MB  (feat @ W)
__device__ float g_zsrc[N_NODES * NH];     // z_src per (n,h)
__device__ float g_zdst[N_NODES * NH];     // z_dst per (n,h)
__device__ int   g_deg[N_NODES];
__device__ int   g_off[N_NODES + 1];
__device__ int   g_cur[N_NODES];
__device__ int   g_ssrc[E_EDGES];          // src id per CSR slot
__device__ float4 g_e2[E_EDGES];           // e2[h=0..3] per CSR slot

// ---------------- 1) GEMM: ft = feat[N,256] @ W[256,128] ---------------------
// BM=64, BN=128(full), BK=16, 256 threads, micro-tile 8x4.
__global__ __launch_bounds__(256) void gemm_kernel(const float* __restrict__ feat,
                                                   const float* __restrict__ W)
{
    __shared__ float As[64][20];   // padded rows (80B, 16B-aligned float4 slots)
    __shared__ float Bs[16][128];

    const int tid = threadIdx.x;
    const int tx = tid & 31;       // 0..31 -> 4 cols each
    const int ty = tid >> 5;       // 0..7  -> 8 rows each
    const int row0 = blockIdx.x * 64;

    const int arow = tid >> 2;     // 0..63
    const int akq  = tid & 3;      // 0..3 (float4 chunk of K-tile)

    float acc[8][4];
#pragma unroll
    for (int i = 0; i < 8; i++)
#pragma unroll
        for (int j = 0; j < 4; j++) acc[i][j] = 0.f;

    for (int k0 = 0; k0 < IN_DIM; k0 += 16) {
        // load A tile 64x16
        float4 av = make_float4(0.f, 0.f, 0.f, 0.f);
        int gr = row0 + arow;
        if (gr < N_NODES)
            av = *reinterpret_cast<const float4*>(&feat[gr * IN_DIM + k0 + akq * 4]);
        *reinterpret_cast<float4*>(&As[arow][akq * 4]) = av;
        // load B tile 16x128
#pragma unroll
        for (int i = 0; i < 2; i++) {
            int f = tid + i * 256;           // float4 index 0..511
            int k = f >> 5, c4 = f & 31;
            *reinterpret_cast<float4*>(&Bs[k][c4 * 4]) =
                *reinterpret_cast<const float4*>(&W[(k0 + k) * HD + c4 * 4]);
        }
        __syncthreads();
#pragma unroll
        for (int k = 0; k < 16; k++) {
            float b[4];
            *reinterpret_cast<float4*>(b) = *reinterpret_cast<float4*>(&Bs[k][tx * 4]);
#pragma unroll
            for (int i = 0; i < 8; i++) {
                float a = As[ty * 8 + i][k];
                acc[i][0] = fmaf(a, b[0], acc[i][0]);
                acc[i][1] = fmaf(a, b[1], acc[i][1]);
                acc[i][2] = fmaf(a, b[2], acc[i][2]);
                acc[i][3] = fmaf(a, b[3], acc[i][3]);
            }
        }
        __syncthreads();
    }
#pragma unroll
    for (int i = 0; i < 8; i++) {
        int gr = row0 + ty * 8 + i;
        if (gr < N_NODES) {
            float4 v = make_float4(acc[i][0], acc[i][1], acc[i][2], acc[i][3]);
            *reinterpret_cast<float4*>(&g_ft[gr * HD + tx * 4]) = v;
        }
    }
}

// ---------------- 2) per-node scalars + z + small outputs --------------------
// one warp per (n,h)
__global__ __launch_bounds__(256) void node_scalar_kernel(
    const float* __restrict__ eps_src, const float* __restrict__ eps_dst,
    const float* __restrict__ mu_src, const float* __restrict__ mu_dst,
    const float* __restrict__ lam_src,
    float* __restrict__ out_mu, float* __restrict__ out_lam)
{
    int warp = (blockIdx.x * blockDim.x + threadIdx.x) >> 5;
    int lane = threadIdx.x & 31;
    if (warp >= N_NODES * NH) return;
    int n = warp >> 2;
    int h = warp & 3;

    float v = g_ft[n * HD + h * ND + lane];
    float ms = v * mu_src[h * ND + lane];
    float ls = v * lam_src[h * ND + lane];
    float md = v * mu_dst[h * ND + lane];
#pragma unroll
    for (int o = 16; o; o >>= 1) {
        ms += __shfl_xor_sync(0xffffffffu, ms, o);
        ls += __shfl_xor_sync(0xffffffffu, ls, o);
        md += __shfl_xor_sync(0xffffffffu, md, o);
    }
    if (lane == 0) {
        // reference replicates lam_src for lam_d -> lam_d == lam_s
        float s = __expf(0.5f * ls);
        g_zsrc[n * NH + h] = eps_src[n * NH + h] * s + ms;
        g_zdst[n * NH + h] = eps_dst[n * NH + h] * s + md;
        out_mu[n * NH + h]  = ms + md;
        out_lam[n * NH + h] = 2.f * ls;
    }
}

// ---------------- 3) CSR build ----------------------------------------------
__global__ void zero_deg_kernel()
{
    int i = blockIdx.x * blockDim.x + threadIdx.x;
    if (i < N_NODES) g_deg[i] = 0;
}

__global__ void count_kernel(const int* __restrict__ dst)
{
    int e = blockIdx.x * blockDim.x + threadIdx.x;
    if (e < E_EDGES) atomicAdd(&g_deg[dst[e]], 1);
}

__global__ __launch_bounds__(1024) void scan_kernel()
{
    __shared__ int warp_sums[32];
    __shared__ int s_carry;
    int tid = threadIdx.x, lane = tid & 31, wid = tid >> 5;
    if (tid == 0) s_carry = 0;
    __syncthreads();
    for (int base = 0; base < N_NODES; base += 1024) {
        int i = base + tid;
        int v = (i < N_NODES) ? g_deg[i] : 0;
        int x = v;
#pragma unroll
        for (int o = 1; o < 32; o <<= 1) {
            int y = __shfl_up_sync(0xffffffffu, x, o);
            if (lane >= o) x += y;
        }
        if (lane == 31) warp_sums[wid] = x;
        __syncthreads();
        if (wid == 0) {
            int s = warp_sums[lane];
#pragma unroll
            for (int o = 1; o < 32; o <<= 1) {
                int y = __shfl_up_sync(0xffffffffu, s, o);
                if (lane >= o) s += y;
            }
            warp_sums[lane] = s;
        }
        __syncthreads();
        int warp_off = (wid > 0) ? warp_sums[wid - 1] : 0;
        int incl = x + warp_off;
        int c0 = s_carry;
        if (i < N_NODES) {
            int excl = c0 + incl - v;
            g_off[i] = excl;
            g_cur[i] = excl;
        }
        __syncthreads();
        if (tid == 1023) s_carry = c0 + incl;
        __syncthreads();
    }
    if (tid == 0) g_off[N_NODES] = s_carry;
}

__global__ void scatter_kernel(const int* __restrict__ src,
                               const int* __restrict__ dst,
                               const float* __restrict__ ppmi)
{
    int e = blockIdx.x * blockDim.x + threadIdx.x;
    if (e >= E_EDGES) return;
    int s = src[e], d = dst[e];
    int pos = atomicAdd(&g_cur[d], 1);
    g_ssrc[pos] = s;
    float lp = logf(ppmi[e]);
    float scale = fmaxf(1.f, logf(fmaxf(1.f, lp)));
    float4 zs = *reinterpret_cast<const float4*>(&g_zsrc[s * NH]);
    float4 zd = *reinterpret_cast<const float4*>(&g_zdst[d * NH]);
    float4 e2;
    float t;
    t = zs.x + zd.x; e2.x = (t > 0.f ? t : NEG_SLOPE * t) * scale;
    t = zs.y + zd.y; e2.y = (t > 0.f ? t : NEG_SLOPE * t) * scale;
    t = zs.z + zd.z; e2.z = (t > 0.f ? t : NEG_SLOPE * t) * scale;
    t = zs.w + zd.w; e2.w = (t > 0.f ? t : NEG_SLOPE * t) * scale;
    g_e2[pos] = e2;
}

// ---------------- 4) per-dst softmax + weighted aggregation ------------------
// one block (128 thr) per dst node; warp h handles head h; thread t owns elem t.
__global__ __launch_bounds__(128) void aggregate_kernel(float* __restrict__ rst)
{
    int n = blockIdx.x;
    int t = threadIdx.x;
    int h = t >> 5, lane = t & 31;
    int beg = g_off[n], end = g_off[n + 1];
    int cnt = end - beg;
    __shared__ float s_max[NH];

    if (cnt == 0) { rst[n * HD + t] = 0.f; return; }

    // phase 1: per-head max
    float m = -CUDART_INF_F;
    for (int i = lane; i < cnt; i += 32) {
        const float* p = reinterpret_cast<const float*>(&g_e2[beg + i]);
        m = fmaxf(m, p[h]);
    }
#pragma unroll
    for (int o = 16; o; o >>= 1) m = fmaxf(m, __shfl_xor_sync(0xffffffffu, m, o));
    if (lane == 0) s_max[h] = m;
    __syncthreads();
    float emax = s_max[h];

    // phase 2: weighted accumulate (no atomics; wsum identical across warp lanes)
    float acc = 0.f, wsum = 0.f;
#pragma unroll 2
    for (int i = 0; i < cnt; i++) {
        int ssrc = g_ssrc[beg + i];
        float e2v = reinterpret_cast<const float*>(&g_e2[beg + i])[h];
        float w = __expf(e2v - emax);
        acc = fmaf(w, g_ft[ssrc * HD + t], acc);
        wsum += w;
    }
    rst[n * HD + t] = acc / wsum;
}

// ---------------- launch ------------------------------------------------------
extern "C" void kernel_launch(void* const* d_in, const int* in_sizes, int n_in,
                              void* d_out, int out_size)
{
    const float* feat    = (const float*)d_in[0];
    const int*   src     = (const int*)  d_in[1];
    const int*   dst     = (const int*)  d_in[2];
    const float* ppmi    = (const float*)d_in[3];
    const float* eps_src = (const float*)d_in[4];
    const float* eps_dst = (const float*)d_in[5];
    const float* W       = (const float*)d_in[6];
    const float* mu_src  = (const float*)d_in[7];
    const float* mu_dst  = (const float*)d_in[8];
    const float* lam_src = (const float*)d_in[9];
    // d_in[10] = lam_dst (unused by reference path)

    float* out     = (float*)d_out;
    float* out_rst = out;                              // [N,H,D]
    float* out_mu  = out + N_NODES * HD;               // [N,H]
    float* out_lam = out + N_NODES * HD + N_NODES * NH;// [N,H]

    gemm_kernel<<<(N_NODES + 63) / 64, 256>>>(feat, W);

    {
        long long total_threads = (long long)N_NODES * NH * 32;
        int blocks = (int)((total_threads + 255) / 256);
        node_scalar_kernel<<<blocks, 256>>>(eps_src, eps_dst, mu_src, mu_dst,
                                            lam_src, out_mu, out_lam);
    }

    zero_deg_kernel<<<(N_NODES + 255) / 256, 256>>>();
    count_kernel<<<(E_EDGES + 255) / 256, 256>>>(dst);
    scan_kernel<<<1, 1024>>>();
    scatter_kernel<<<(E_EDGES + 255) / 256, 256>>>(src, dst, ppmi);
    aggregate_kernel<<<N_NODES, 128>>>(out_rst);
}

// round 2
// speedup vs baseline: 1.3288x; 1.3288x over previous
#include <cuda_runtime.h>
#include <cuda_fp16.h>
#include <math_constants.h>

#define N_NODES 50000
#define E_EDGES 800000
#define IN_DIM  256
#define NH      4
#define ND      32
#define HD      128
#define NEG_SLOPE 0.2f

#define SCAN_BLK 1024
#define NUM_SCAN_BLOCKS ((N_NODES + SCAN_BLK - 1) / SCAN_BLK)   // 49

// ---------------- scratch (device globals; no runtime allocation) -------------
__device__ float  g_ft[N_NODES * HD];       // fp32 ft (for node scalars)
__device__ __half g_fth[N_NODES * HD];      // fp16 ft (for the big gather)
__device__ float  g_zsrc[N_NODES * NH];
__device__ float  g_zdst[N_NODES * NH];
__device__ int    g_deg[N_NODES];
__device__ int    g_off[N_NODES + 1];
__device__ int    g_cur[N_NODES];
__device__ int    g_bsum[64];
__device__ int    g_bpre[64];
__device__ int    g_ssrc[E_EDGES];          // src id per CSR slot
__device__ float4 g_w[E_EDGES];             // exp(e2)[h=0..3] per CSR slot

// ---------------- 1) GEMM: ft = feat[N,256] @ W[256,128] ---------------------
// BM=128, BN=128, BK=32, 256 threads, 8x8 micro-tile.
__global__ __launch_bounds__(256) void gemm_kernel(const float* __restrict__ feat,
                                                   const float* __restrict__ W)
{
    __shared__ float As[32][132];   // [k][m], padded
    __shared__ float Bs[32][128];   // [k][n]

    const int tid = threadIdx.x;
    const int tx = tid & 15;        // 0..15 -> cols tx*4 and 64+tx*4
    const int ty = tid >> 4;        // 0..15 -> rows ty*4 and 64+ty*4
    const int row0 = blockIdx.x * 128;

    float acc[8][8];
#pragma unroll
    for (int i = 0; i < 8; i++)
#pragma unroll
        for (int j = 0; j < 8; j++) acc[i][j] = 0.f;

    for (int k0 = 0; k0 < IN_DIM; k0 += 32) {
        // A tile: 128 rows x 32 k  (transpose into As[k][m])
#pragma unroll
        for (int i = 0; i < 4; i++) {
            int f = tid + i * 256;          // 0..1023 float4 index
            int r = f >> 3;                 // 0..127
            int q = f & 7;                  // k-chunk (4 floats)
            int gr = row0 + r;
            float4 av = make_float4(0.f, 0.f, 0.f, 0.f);
            if (gr < N_NODES)
                av = *reinterpret_cast<const float4*>(&feat[gr * IN_DIM + k0 + q * 4]);
            As[q * 4 + 0][r] = av.x;
            As[q * 4 + 1][r] = av.y;
            As[q * 4 + 2][r] = av.z;
            As[q * 4 + 3][r] = av.w;
        }
        // B tile: 32 k x 128 n
#pragma unroll
        for (int i = 0; i < 4; i++) {
            int f = tid + i * 256;
            int k = f >> 5, c4 = f & 31;
            *reinterpret_cast<float4*>(&Bs[k][c4 * 4]) =
                *reinterpret_cast<const float4*>(&W[(k0 + k) * HD + c4 * 4]);
        }
        __syncthreads();
#pragma unroll
        for (int k = 0; k < 32; k++) {
            float a[8], b[8];
            *reinterpret_cast<float4*>(a)     = *reinterpret_cast<float4*>(&As[k][ty * 4]);
            *reinterpret_cast<float4*>(a + 4) = *reinterpret_cast<float4*>(&As[k][64 + ty * 4]);
            *reinterpret_cast<float4*>(b)     = *reinterpret_cast<float4*>(&Bs[k][tx * 4]);
            *reinterpret_cast<float4*>(b + 4) = *reinterpret_cast<float4*>(&Bs[k][64 + tx * 4]);
#pragma unroll
            for (int i = 0; i < 8; i++)
#pragma unroll
                for (int j = 0; j < 8; j++)
                    acc[i][j] = fmaf(a[i], b[j], acc[i][j]);
        }
        __syncthreads();
    }

    // epilogue: fp32 + fp16 stores
#pragma unroll
    for (int ri = 0; ri < 2; ri++) {
#pragma unroll
        for (int i = 0; i < 4; i++) {
            int gr = row0 + ri * 64 + ty * 4 + i;
            if (gr >= N_NODES) continue;
            int ai = ri * 4 + i;
#pragma unroll
            for (int cj = 0; cj < 2; cj++) {
                int col = cj * 64 + tx * 4;
                float4 v = make_float4(acc[ai][cj * 4 + 0], acc[ai][cj * 4 + 1],
                                       acc[ai][cj * 4 + 2], acc[ai][cj * 4 + 3]);
                *reinterpret_cast<float4*>(&g_ft[gr * HD + col]) = v;
                __half2 p0 = __floats2half2_rn(v.x, v.y);
                __half2 p1 = __floats2half2_rn(v.z, v.w);
                *reinterpret_cast<__half2*>(&g_fth[gr * HD + col])     = p0;
                *reinterpret_cast<__half2*>(&g_fth[gr * HD + col + 2]) = p1;
            }
        }
    }
}

// ---------------- 2) per-node scalars + z + small outputs --------------------
__global__ __launch_bounds__(256) void node_scalar_kernel(
    const float* __restrict__ eps_src, const float* __restrict__ eps_dst,
    const float* __restrict__ mu_src, const float* __restrict__ mu_dst,
    const float* __restrict__ lam_src,
    float* __restrict__ out_mu, float* __restrict__ out_lam)
{
    int warp = (blockIdx.x * blockDim.x + threadIdx.x) >> 5;
    int lane = threadIdx.x & 31;
    if (warp >= N_NODES * NH) return;
    int n = warp >> 2;
    int h = warp & 3;

    float v = g_ft[n * HD + h * ND + lane];
    float ms = v * mu_src[h * ND + lane];
    float ls = v * lam_src[h * ND + lane];
    float md = v * mu_dst[h * ND + lane];
#pragma unroll
    for (int o = 16; o; o >>= 1) {
        ms += __shfl_xor_sync(0xffffffffu, ms, o);
        ls += __shfl_xor_sync(0xffffffffu, ls, o);
        md += __shfl_xor_sync(0xffffffffu, md, o);
    }
    if (lane == 0) {
        float s = __expf(0.5f * ls);       // lam_d == lam_s (ref replicates lam_src)
        g_zsrc[n * NH + h] = eps_src[n * NH + h] * s + ms;
        g_zdst[n * NH + h] = eps_dst[n * NH + h] * s + md;
        out_mu[n * NH + h]  = ms + md;
        out_lam[n * NH + h] = 2.f * ls;
    }
}

// ---------------- 3) CSR build ----------------------------------------------
__global__ void zero_deg_kernel()
{
    int i = blockIdx.x * blockDim.x + threadIdx.x;
    if (i < N_NODES) g_deg[i] = 0;
}

__global__ void count_kernel(const int* __restrict__ dst)
{
    int e4 = blockIdx.x * blockDim.x + threadIdx.x;
    int base = e4 * 4;
    if (base + 3 < E_EDGES) {
        int4 d = *reinterpret_cast<const int4*>(&dst[base]);
        atomicAdd(&g_deg[d.x], 1);
        atomicAdd(&g_deg[d.y], 1);
        atomicAdd(&g_deg[d.z], 1);
        atomicAdd(&g_deg[d.w], 1);
    } else {
        for (int e = base; e < E_EDGES; e++) atomicAdd(&g_deg[dst[e]], 1);
    }
}

// scan level 1: per-block exclusive scan + block sums
__global__ __launch_bounds__(SCAN_BLK) void scan1_kernel()
{
    __shared__ int warp_sums[32];
    int tid = threadIdx.x, lane = tid & 31, wid = tid >> 5;
    int i = blockIdx.x * SCAN_BLK + tid;
    int v = (i < N_NODES) ? g_deg[i] : 0;
    int x = v;
#pragma unroll
    for (int o = 1; o < 32; o <<= 1) {
        int y = __shfl_up_sync(0xffffffffu, x, o);
        if (lane >= o) x += y;
    }
    if (lane == 31) warp_sums[wid] = x;
    __syncthreads();
    if (wid == 0) {
        int s = warp_sums[lane];
#pragma unroll
        for (int o = 1; o < 32; o <<= 1) {
            int y = __shfl_up_sync(0xffffffffu, s, o);
            if (lane >= o) s += y;
        }
        warp_sums[lane] = s;
    }
    __syncthreads();
    int warp_off = (wid > 0) ? warp_sums[wid - 1] : 0;
    int incl = x + warp_off;
    if (i < N_NODES) g_off[i] = incl - v;      // local exclusive
    if (tid == SCAN_BLK - 1) g_bsum[blockIdx.x] = incl;
}

// scan level 2: scan the 49 block sums (1 block, 64 threads)
__global__ __launch_bounds__(64) void scan2_kernel()
{
    __shared__ int w0sum;
    int t = threadIdx.x, lane = t & 31, wid = t >> 5;
    int v = (t < NUM_SCAN_BLOCKS) ? g_bsum[t] : 0;
    int x = v;
#pragma unroll
    for (int o = 1; o < 32; o <<= 1) {
        int y = __shfl_up_sync(0xffffffffu, x, o);
        if (lane >= o) x += y;
    }
    if (t == 31) w0sum = x;
    __syncthreads();
    int incl = x + ((wid == 1) ? w0sum : 0);
    if (t < NUM_SCAN_BLOCKS) g_bpre[t] = incl - v;
    if (t == 63) g_off[N_NODES] = incl;        // grand total (== E_EDGES)
}

// scan level 3: add block prefixes, init cursors
__global__ __launch_bounds__(SCAN_BLK) void scan3_kernel()
{
    int i = blockIdx.x * SCAN_BLK + threadIdx.x;
    if (i < N_NODES) {
        int o = g_off[i] + g_bpre[blockIdx.x];
        g_off[i] = o;
        g_cur[i] = o;
    }
}

// ---------------- scatter: CSR payload + w = exp(e2) -------------------------
__global__ void scatter_kernel(const int* __restrict__ src,
                               const int* __restrict__ dst,
                               const float* __restrict__ ppmi)
{
    int e = blockIdx.x * blockDim.x + threadIdx.x;
    if (e >= E_EDGES) return;
    int s = src[e], d = dst[e];
    int pos = atomicAdd(&g_cur[d], 1);
    g_ssrc[pos] = s;
    float lp = logf(ppmi[e]);
    float scale = fmaxf(1.f, logf(fmaxf(1.f, lp)));
    float4 zs = *reinterpret_cast<const float4*>(&g_zsrc[s * NH]);
    float4 zd = *reinterpret_cast<const float4*>(&g_zdst[d * NH]);
    float4 w;
    float t;
    t = zs.x + zd.x; w.x = __expf((t > 0.f ? t : NEG_SLOPE * t) * scale);
    t = zs.y + zd.y; w.y = __expf((t > 0.f ? t : NEG_SLOPE * t) * scale);
    t = zs.z + zd.z; w.z = __expf((t > 0.f ? t : NEG_SLOPE * t) * scale);
    t = zs.w + zd.w; w.w = __expf((t > 0.f ? t : NEG_SLOPE * t) * scale);
    g_w[pos] = w;
}

// ---------------- aggregate: per-dst weighted mean (no max pass) -------------
// one block (128 thr) per dst node; thread t owns output element t; head h=t>>5.
__global__ __launch_bounds__(128) void aggregate_kernel(float* __restrict__ rst)
{
    int n = blockIdx.x;
    int t = threadIdx.x;
    int h = t >> 5;
    int beg = g_off[n], end = g_off[n + 1];
    int cnt = end - beg;

    if (cnt == 0) { rst[n * HD + t] = 0.f; return; }

    const float* wbase = reinterpret_cast<const float*>(g_w);
    float acc = 0.f, wsum = 0.f;
#pragma unroll 4
    for (int i = 0; i < cnt; i++) {
        int s = __ldg(&g_ssrc[beg + i]);
        float w = __ldg(&wbase[(beg + i) * 4 + h]);
        wsum += w;
        acc = fmaf(w, __half2float(g_fth[s * HD + t]), acc);
    }
    rst[n * HD + t] = acc / wsum;
}

// ---------------- launch ------------------------------------------------------
extern "C" void kernel_launch(void* const* d_in, const int* in_sizes, int n_in,
                              void* d_out, int out_size)
{
    const float* feat    = (const float*)d_in[0];
    const int*   src     = (const int*)  d_in[1];
    const int*   dst     = (const int*)  d_in[2];
    const float* ppmi    = (const float*)d_in[3];
    const float* eps_src = (const float*)d_in[4];
    const float* eps_dst = (const float*)d_in[5];
    const float* W       = (const float*)d_in[6];
    const float* mu_src  = (const float*)d_in[7];
    const float* mu_dst  = (const float*)d_in[8];
    const float* lam_src = (const float*)d_in[9];

    float* out     = (float*)d_out;
    float* out_rst = out;
    float* out_mu  = out + N_NODES * HD;
    float* out_lam = out + N_NODES * HD + N_NODES * NH;

    gemm_kernel<<<(N_NODES + 127) / 128, 256>>>(feat, W);

    {
        long long total_threads = (long long)N_NODES * NH * 32;
        int blocks = (int)((total_threads + 255) / 256);
        node_scalar_kernel<<<blocks, 256>>>(eps_src, eps_dst, mu_src, mu_dst,
                                            lam_src, out_mu, out_lam);
    }

    zero_deg_kernel<<<(N_NODES + 255) / 256, 256>>>();
    count_kernel<<<((E_EDGES / 4) + 255) / 256, 256>>>(dst);
    scan1_kernel<<<NUM_SCAN_BLOCKS, SCAN_BLK>>>();
    scan2_kernel<<<1, 64>>>();
    scan3_kernel<<<NUM_SCAN_BLOCKS, SCAN_BLK>>>();
    scatter_kernel<<<(E_EDGES + 255) / 256, 256>>>(src, dst, ppmi);
    aggregate_kernel<<<N_NODES, 128>>>(out_rst);
}

// round 3
// speedup vs baseline: 1.8499x; 1.3922x over previous
#include <cuda_runtime.h>
#include <cuda_fp16.h>
#include <mma.h>
#include <math_constants.h>

using namespace nvcuda;

#define N_NODES 50000
#define E_EDGES 800000
#define IN_DIM  256
#define NH      4
#define ND      32
#define HD      128
#define NEG_SLOPE 0.2f

#define SCAN_BLK 1024
#define NUM_SCAN_BLOCKS ((N_NODES + SCAN_BLK - 1) / SCAN_BLK)   // 49

#define BN_EXT 144          // 128 ft cols + 12 scalar cols + 4 pad
#define GEMM_SMEM_BYTES (128 * 148 * 4)   // 75776 B: epilogue stage; covers A+B too

// ---------------- scratch (device globals; no runtime allocation) -------------
__device__ __half g_Wext[IN_DIM * BN_EXT];  // [256][144] fp16: W | P | pad
__device__ __half g_fth[N_NODES * HD];      // fp16 ft (for the big gather)
__device__ float  g_S[N_NODES * 12];        // per-node scalar dots (fp32 from acc)
__device__ float  g_zsrc[N_NODES * NH];
__device__ float  g_zdst[N_NODES * NH];
__device__ int    g_deg[N_NODES];
__device__ int    g_off[N_NODES + 1];
__device__ int    g_cur[N_NODES];
__device__ int    g_bsum[64];
__device__ int    g_bpre[64];
__device__ int    g_ssrc[E_EDGES];          // src id per CSR slot
__device__ float4 g_w[E_EDGES];             // exp(e2)[h=0..3] per CSR slot

// ---------------- 0) build Wext = [W (fp16) | P (fp16) | 0] ------------------
// P[k][t*4+h] = sum_d W[k][h*32+d] * vec_t[h*32+d], t in {mu_src, mu_dst, lam_src}
__global__ void prep_w_kernel(const float* __restrict__ W,
                              const float* __restrict__ mu_src,
                              const float* __restrict__ mu_dst,
                              const float* __restrict__ lam_src)
{
    int idx = blockIdx.x * blockDim.x + threadIdx.x;
    if (idx >= IN_DIM * BN_EXT) return;
    int k = idx / BN_EXT, c = idx % BN_EXT;
    float v = 0.f;
    if (c < HD) {
        v = W[k * HD + c];
    } else if (c < HD + 12) {
        int t = (c - HD) >> 2, h = (c - HD) & 3;
        const float* vec = (t == 0) ? mu_src : ((t == 1) ? mu_dst : lam_src);
        float s = 0.f;
#pragma unroll
        for (int d = 0; d < ND; d++)
            s += W[k * HD + h * ND + d] * vec[h * ND + d];
        v = s;
    }
    g_Wext[k * BN_EXT + c] = __float2half(v);
}

// ---------------- 1) WMMA GEMM: [ft | S] = feat @ Wext -----------------------
// block: 128 rows x 144 cols, 8 warps (each warp: 16 rows x 144 cols = 9 n-tiles)
extern __shared__ char smem_raw[];

__global__ void __launch_bounds__(256) gemm_wmma_kernel(const float* __restrict__ feat)
{
    // mainloop layout: sA [128][24] half at 0 (6144B), sB [16][152] half at 8192
    __half (*sA)[24]  = reinterpret_cast<__half(*)[24]>(smem_raw);
    __half (*sB)[152] = reinterpret_cast<__half(*)[152]>(smem_raw + 8192);
    float* sC = reinterpret_cast<float*>(smem_raw);       // epilogue reuse [128][148]

    const int tid  = threadIdx.x;
    const int warp = tid >> 5;
    const int row0 = blockIdx.x * 128;

    wmma::fragment<wmma::accumulator, 16, 16, 16, float> acc[9];
#pragma unroll
    for (int j = 0; j < 9; j++) wmma::fill_fragment(acc[j], 0.f);

    for (int k0 = 0; k0 < IN_DIM; k0 += 16) {
        // A tile: 128 x 16 fp32 -> fp16 (convert in flight)
#pragma unroll
        for (int i = 0; i < 2; i++) {
            int f = tid + i * 256;        // 0..511 float4 slots
            int r = f >> 2, q = f & 3;
            int gr = row0 + r;
            float4 v = make_float4(0.f, 0.f, 0.f, 0.f);
            if (gr < N_NODES)
                v = *reinterpret_cast<const float4*>(&feat[gr * IN_DIM + k0 + q * 4]);
            __half2* d = reinterpret_cast<__half2*>(&sA[r][q * 4]);
            d[0] = __floats2half2_rn(v.x, v.y);
            d[1] = __floats2half2_rn(v.z, v.w);
        }
        // B tile: 16 x 144 fp16 (288 uint4)
        for (int f = tid; f < 288; f += 256) {
            int r = f / 18, c = f % 18;   // c indexes 8-half chunks
            *reinterpret_cast<uint4*>(&sB[r][c * 8]) =
                *reinterpret_cast<const uint4*>(&g_Wext[(k0 + r) * BN_EXT + c * 8]);
        }
        __syncthreads();

        wmma::fragment<wmma::matrix_a, 16, 16, 16, __half, wmma::row_major> af;
        wmma::load_matrix_sync(af, &sA[warp * 16][0], 24);
#pragma unroll
        for (int j = 0; j < 9; j++) {
            wmma::fragment<wmma::matrix_b, 16, 16, 16, __half, wmma::row_major> bf;
            wmma::load_matrix_sync(bf, &sB[0][j * 16], 152);
            wmma::mma_sync(acc[j], af, bf, acc[j]);
        }
        __syncthreads();
    }

    // epilogue: stage fp32 in smem, then split-store fp16 ft + fp32 S
#pragma unroll
    for (int j = 0; j < 9; j++)
        wmma::store_matrix_sync(&sC[(warp * 16) * 148 + j * 16], acc[j], 148,
                                wmma::mem_row_major);
    __syncthreads();

    for (int idx = tid; idx < 128 * 64; idx += 256) {
        int r = idx >> 6, c2 = idx & 63;
        int gr = row0 + r;
        if (gr < N_NODES) {
            __half2 hv = __floats2half2_rn(sC[r * 148 + c2 * 2], sC[r * 148 + c2 * 2 + 1]);
            *reinterpret_cast<__half2*>(&g_fth[gr * HD + c2 * 2]) = hv;
        }
    }
    for (int idx = tid; idx < 128 * 12; idx += 256) {
        int r = idx / 12, c = idx % 12;
        int gr = row0 + r;
        if (gr < N_NODES) g_S[gr * 12 + c] = sC[r * 148 + 128 + c];
    }
}

// ---------------- 2) per-node z + small outputs (pointwise) ------------------
__global__ void node_scalar_kernel(const float* __restrict__ eps_src,
                                   const float* __restrict__ eps_dst,
                                   float* __restrict__ out_mu,
                                   float* __restrict__ out_lam)
{
    int i = blockIdx.x * blockDim.x + threadIdx.x;   // n*4 + h
    if (i >= N_NODES * NH) return;
    int n = i >> 2, h = i & 3;
    float ms = g_S[n * 12 + h];
    float md = g_S[n * 12 + 4 + h];
    float ls = g_S[n * 12 + 8 + h];
    float s = __expf(0.5f * ls);      // lam_d == lam_s (ref replicates lam_src)
    g_zsrc[i] = eps_src[i] * s + ms;
    g_zdst[i] = eps_dst[i] * s + md;
    out_mu[i]  = ms + md;
    out_lam[i] = 2.f * ls;
}

// ---------------- 3) CSR build ----------------------------------------------
__global__ void zero_deg_kernel()
{
    int i = blockIdx.x * blockDim.x + threadIdx.x;
    if (i < N_NODES) g_deg[i] = 0;
}

__global__ void count_kernel(const int* __restrict__ dst)
{
    int e4 = blockIdx.x * blockDim.x + threadIdx.x;
    int base = e4 * 4;
    if (base + 3 < E_EDGES) {
        int4 d = *reinterpret_cast<const int4*>(&dst[base]);
        atomicAdd(&g_deg[d.x], 1);
        atomicAdd(&g_deg[d.y], 1);
        atomicAdd(&g_deg[d.z], 1);
        atomicAdd(&g_deg[d.w], 1);
    } else {
        for (int e = base; e < E_EDGES; e++) atomicAdd(&g_deg[dst[e]], 1);
    }
}

__global__ __launch_bounds__(SCAN_BLK) void scan1_kernel()
{
    __shared__ int warp_sums[32];
    int tid = threadIdx.x, lane = tid & 31, wid = tid >> 5;
    int i = blockIdx.x * SCAN_BLK + tid;
    int v = (i < N_NODES) ? g_deg[i] : 0;
    int x = v;
#pragma unroll
    for (int o = 1; o < 32; o <<= 1) {
        int y = __shfl_up_sync(0xffffffffu, x, o);
        if (lane >= o) x += y;
    }
    if (lane == 31) warp_sums[wid] = x;
    __syncthreads();
    if (wid == 0) {
        int s = warp_sums[lane];
#pragma unroll
        for (int o = 1; o < 32; o <<= 1) {
            int y = __shfl_up_sync(0xffffffffu, s, o);
            if (lane >= o) s += y;
        }
        warp_sums[lane] = s;
    }
    __syncthreads();
    int warp_off = (wid > 0) ? warp_sums[wid - 1] : 0;
    int incl = x + warp_off;
    if (i < N_NODES) g_off[i] = incl - v;
    if (tid == SCAN_BLK - 1) g_bsum[blockIdx.x] = incl;
}

__global__ __launch_bounds__(64) void scan2_kernel()
{
    __shared__ int w0sum;
    int t = threadIdx.x, lane = t & 31, wid = t >> 5;
    int v = (t < NUM_SCAN_BLOCKS) ? g_bsum[t] : 0;
    int x = v;
#pragma unroll
    for (int o = 1; o < 32; o <<= 1) {
        int y = __shfl_up_sync(0xffffffffu, x, o);
        if (lane >= o) x += y;
    }
    if (t == 31) w0sum = x;
    __syncthreads();
    int incl = x + ((wid == 1) ? w0sum : 0);
    if (t < NUM_SCAN_BLOCKS) g_bpre[t] = incl - v;
    if (t == 63) g_off[N_NODES] = incl;
}

__global__ __launch_bounds__(SCAN_BLK) void scan3_kernel()
{
    int i = blockIdx.x * SCAN_BLK + threadIdx.x;
    if (i < N_NODES) {
        int o = g_off[i] + g_bpre[blockIdx.x];
        g_off[i] = o;
        g_cur[i] = o;
    }
}

// ---------------- scatter: CSR payload + w = exp(e2) -------------------------
__global__ void scatter_kernel(const int* __restrict__ src,
                               const int* __restrict__ dst,
                               const float* __restrict__ ppmi)
{
    int e = blockIdx.x * blockDim.x + threadIdx.x;
    if (e >= E_EDGES) return;
    int s = src[e], d = dst[e];
    int pos = atomicAdd(&g_cur[d], 1);
    g_ssrc[pos] = s;
    float lp = logf(ppmi[e]);
    float scale = fmaxf(1.f, logf(fmaxf(1.f, lp)));
    float4 zs = *reinterpret_cast<const float4*>(&g_zsrc[s * NH]);
    float4 zd = *reinterpret_cast<const float4*>(&g_zdst[d * NH]);
    float4 w;
    float t;
    t = zs.x + zd.x; w.x = __expf((t > 0.f ? t : NEG_SLOPE * t) * scale);
    t = zs.y + zd.y; w.y = __expf((t > 0.f ? t : NEG_SLOPE * t) * scale);
    t = zs.z + zd.z; w.z = __expf((t > 0.f ? t : NEG_SLOPE * t) * scale);
    t = zs.w + zd.w; w.w = __expf((t > 0.f ? t : NEG_SLOPE * t) * scale);
    g_w[pos] = w;
}

// ---------------- aggregate: per-dst weighted mean ---------------------------
__global__ __launch_bounds__(128) void aggregate_kernel(float* __restrict__ rst)
{
    int n = blockIdx.x;
    int t = threadIdx.x;
    int h = t >> 5;
    int beg = g_off[n], end = g_off[n + 1];
    int cnt = end - beg;

    if (cnt == 0) { rst[n * HD + t] = 0.f; return; }

    const float* wbase = reinterpret_cast<const float*>(g_w);
    float acc = 0.f, wsum = 0.f;
#pragma unroll 4
    for (int i = 0; i < cnt; i++) {
        int s = __ldg(&g_ssrc[beg + i]);
        float w = __ldg(&wbase[(beg + i) * 4 + h]);
        wsum += w;
        acc = fmaf(w, __half2float(g_fth[s * HD + t]), acc);
    }
    rst[n * HD + t] = acc / wsum;
}

// ---------------- launch ------------------------------------------------------
extern "C" void kernel_launch(void* const* d_in, const int* in_sizes, int n_in,
                              void* d_out, int out_size)
{
    const float* feat    = (const float*)d_in[0];
    const int*   src     = (const int*)  d_in[1];
    const int*   dst     = (const int*)  d_in[2];
    const float* ppmi    = (const float*)d_in[3];
    const float* eps_src = (const float*)d_in[4];
    const float* eps_dst = (const float*)d_in[5];
    const float* W       = (const float*)d_in[6];
    const float* mu_src  = (const float*)d_in[7];
    const float* mu_dst  = (const float*)d_in[8];
    const float* lam_src = (const float*)d_in[9];

    float* out     = (float*)d_out;
    float* out_rst = out;
    float* out_mu  = out + N_NODES * HD;
    float* out_lam = out + N_NODES * HD + N_NODES * NH;

    prep_w_kernel<<<(IN_DIM * BN_EXT + 255) / 256, 256>>>(W, mu_src, mu_dst, lam_src);

    cudaFuncSetAttribute(gemm_wmma_kernel,
                         cudaFuncAttributeMaxDynamicSharedMemorySize, GEMM_SMEM_BYTES);
    gemm_wmma_kernel<<<(N_NODES + 127) / 128, 256, GEMM_SMEM_BYTES>>>(feat);

    node_scalar_kernel<<<(N_NODES * NH + 255) / 256, 256>>>(eps_src, eps_dst,
                                                            out_mu, out_lam);

    zero_deg_kernel<<<(N_NODES + 255) / 256, 256>>>();
    count_kernel<<<((E_EDGES / 4) + 255) / 256, 256>>>(dst);
    scan1_kernel<<<NUM_SCAN_BLOCKS, SCAN_BLK>>>();
    scan2_kernel<<<1, 64>>>();
    scan3_kernel<<<NUM_SCAN_BLOCKS, SCAN_BLK>>>();
    scatter_kernel<<<(E_EDGES + 255) / 256, 256>>>(src, dst, ppmi);
    aggregate_kernel<<<N_NODES, 128>>>(out_rst);
}

// round 4
// speedup vs baseline: 2.2466x; 1.2144x over previous
#include <cuda_runtime.h>
#include <cuda_fp16.h>
#include <mma.h>
#include <math_constants.h>

using namespace nvcuda;

#define N_NODES 50000
#define E_EDGES 800000
#define IN_DIM  256
#define NH      4
#define ND      32
#define HD      128
#define NEG_SLOPE 0.2f

#define SCAN_BLK 1024
#define NUM_SCAN_BLOCKS ((N_NODES + SCAN_BLK - 1) / SCAN_BLK)   // 49

#define BN_EXT 144          // 128 ft cols + 12 scalar cols + 4 pad
#define BK     32
#define GEMM_BLOCKS ((N_NODES + 127) / 128)

// smem layout (mainloop):
//   sA[2]: 128 x 40 half   (10240 B each)  at 0 / 10240
//   sB[2]:  32 x 152 half  ( 9728 B each)  at 20480 / 30208
// epilogue reuses base as float sC[128][148] = 75776 B
#define SA_OFF(buf)  ((buf) * 10240)
#define SB_OFF(buf)  (20480 + (buf) * 9728)
#define GEMM_SMEM_BYTES (128 * 148 * 4)   // 75776

// ---------------- scratch (device globals; no runtime allocation) -------------
__device__ __half g_Wext[IN_DIM * BN_EXT];  // [256][144] fp16: W | P | pad
__device__ __half g_fth[N_NODES * HD];      // fp16 ft (for the big gather)
__device__ float  g_zsrc[N_NODES * NH];
__device__ float  g_zdst[N_NODES * NH];
__device__ int    g_deg[N_NODES];           // zero at load; re-zeroed by scan each run
__device__ int    g_off[N_NODES + 1];
__device__ int    g_cur[N_NODES];
__device__ volatile int g_flag[64];         // zero at load; reset by scan each run
__device__ int    g_done;                   // zero at load; reset by scan each run
__device__ int    g_ssrc[E_EDGES];          // src id per CSR slot
__device__ float4 g_w[E_EDGES];             // exp(e2)[h=0..3] per CSR slot

// ---------------- 0) build Wext = [W (fp16) | P (fp16) | 0] ------------------
__global__ void prep_w_kernel(const float* __restrict__ W,
                              const float* __restrict__ mu_src,
                              const float* __restrict__ mu_dst,
                              const float* __restrict__ lam_src)
{
    int idx = blockIdx.x * blockDim.x + threadIdx.x;
    if (idx >= IN_DIM * BN_EXT) return;
    int k = idx / BN_EXT, c = idx % BN_EXT;
    float v = 0.f;
    if (c < HD) {
        v = W[k * HD + c];
    } else if (c < HD + 12) {
        int t = (c - HD) >> 2, h = (c - HD) & 3;
        const float* vec = (t == 0) ? mu_src : ((t == 1) ? mu_dst : lam_src);
        float s = 0.f;
#pragma unroll
        for (int d = 0; d < ND; d++)
            s += W[k * HD + h * ND + d] * vec[h * ND + d];
        v = s;
    }
    g_Wext[k * BN_EXT + c] = __float2half(v);
}

// ---------------- 1) WMMA GEMM + fused node scalars --------------------------
extern __shared__ char smem_raw[];

__global__ void __launch_bounds__(256) gemm_wmma_kernel(
    const float* __restrict__ feat,
    const float* __restrict__ eps_src, const float* __restrict__ eps_dst,
    float* __restrict__ out_mu, float* __restrict__ out_lam)
{
    const int tid  = threadIdx.x;
    const int warp = tid >> 5;
    const int row0 = blockIdx.x * 128;

    // prefetch registers
    float4 aReg[4];
    uint4  bReg[3];

    // thread mapping for A: f = tid + i*256, i<4 -> r=f>>3 (0..127), q=f&7
    // thread mapping for B: f = tid + i*256, f<576 -> r=f/18, c=f%18 (8-half chunks)

    wmma::fragment<wmma::accumulator, 16, 16, 16, float> acc[9];
#pragma unroll
    for (int j = 0; j < 9; j++) wmma::fill_fragment(acc[j], 0.f);

    auto load_regs = [&](int k0) {
#pragma unroll
        for (int i = 0; i < 4; i++) {
            int f = tid + i * 256;
            int r = f >> 3, q = f & 7;
            int gr = row0 + r;
            aReg[i] = make_float4(0.f, 0.f, 0.f, 0.f);
            if (gr < N_NODES)
                aReg[i] = *reinterpret_cast<const float4*>(&feat[gr * IN_DIM + k0 + q * 4]);
        }
#pragma unroll
        for (int i = 0; i < 3; i++) {
            int f = tid + i * 256;
            if (f < 576) {
                int r = f / 18, c = f % 18;
                bReg[i] = *reinterpret_cast<const uint4*>(&g_Wext[(k0 + r) * BN_EXT + c * 8]);
            }
        }
    };
    auto store_regs = [&](int buf) {
        __half* sA = reinterpret_cast<__half*>(smem_raw + SA_OFF(buf));
        __half* sB = reinterpret_cast<__half*>(smem_raw + SB_OFF(buf));
#pragma unroll
        for (int i = 0; i < 4; i++) {
            int f = tid + i * 256;
            int r = f >> 3, q = f & 7;
            __half2* d = reinterpret_cast<__half2*>(&sA[r * 40 + q * 4]);
            d[0] = __floats2half2_rn(aReg[i].x, aReg[i].y);
            d[1] = __floats2half2_rn(aReg[i].z, aReg[i].w);
        }
#pragma unroll
        for (int i = 0; i < 3; i++) {
            int f = tid + i * 256;
            if (f < 576) {
                int r = f / 18, c = f % 18;
                *reinterpret_cast<uint4*>(&sB[r * 152 + c * 8]) = bReg[i];
            }
        }
    };

    load_regs(0);
    store_regs(0);
    __syncthreads();

    for (int it = 0; it < IN_DIM / BK; it++) {          // 8 iterations
        int cur = it & 1;
        if (it < 7) load_regs((it + 1) * BK);           // LDGs in flight during MMA

        const __half* sA = reinterpret_cast<const __half*>(smem_raw + SA_OFF(cur));
        const __half* sB = reinterpret_cast<const __half*>(smem_raw + SB_OFF(cur));
#pragma unroll
        for (int kk = 0; kk < BK; kk += 16) {
            wmma::fragment<wmma::matrix_a, 16, 16, 16, __half, wmma::row_major> af;
            wmma::load_matrix_sync(af, sA + (warp * 16) * 40 + kk, 40);
#pragma unroll
            for (int j = 0; j < 9; j++) {
                wmma::fragment<wmma::matrix_b, 16, 16, 16, __half, wmma::row_major> bf;
                wmma::load_matrix_sync(bf, sB + kk * 152 + j * 16, 152);
                wmma::mma_sync(acc[j], af, bf, acc[j]);
            }
        }
        if (it < 7) store_regs(cur ^ 1);
        __syncthreads();
    }

    // epilogue: stage fp32 in smem (reuse), then split-store
    float* sC = reinterpret_cast<float*>(smem_raw);
#pragma unroll
    for (int j = 0; j < 9; j++)
        wmma::store_matrix_sync(&sC[(warp * 16) * 148 + j * 16], acc[j], 148,
                                wmma::mem_row_major);
    __syncthreads();

    // ft cols 0..127 as fp16
    for (int idx = tid; idx < 128 * 64; idx += 256) {
        int r = idx >> 6, c2 = idx & 63;
        int gr = row0 + r;
        if (gr < N_NODES) {
            __half2 hv = __floats2half2_rn(sC[r * 148 + c2 * 2], sC[r * 148 + c2 * 2 + 1]);
            *reinterpret_cast<__half2*>(&g_fth[gr * HD + c2 * 2]) = hv;
        }
    }
    // fused node scalars from cols 128..139
    for (int idx = tid; idx < 128 * NH; idx += 256) {
        int r = idx >> 2, h = idx & 3;
        int gr = row0 + r;
        if (gr < N_NODES) {
            float ms = sC[r * 148 + 128 + h];
            float md = sC[r * 148 + 132 + h];
            float ls = sC[r * 148 + 136 + h];
            float s = __expf(0.5f * ls);        // lam_d == lam_s (ref replicates lam_src)
            int o = gr * NH + h;
            g_zsrc[o] = eps_src[o] * s + ms;
            g_zdst[o] = eps_dst[o] * s + md;
            out_mu[o]  = ms + md;
            out_lam[o] = 2.f * ls;
        }
    }
}

// ---------------- 2) count (g_deg arrives zeroed; invariant) ------------------
__global__ void count_kernel(const int* __restrict__ dst)
{
    int e4 = blockIdx.x * blockDim.x + threadIdx.x;
    int base = e4 * 4;
    if (base + 3 < E_EDGES) {
        int4 d = *reinterpret_cast<const int4*>(&dst[base]);
        atomicAdd(&g_deg[d.x], 1);
        atomicAdd(&g_deg[d.y], 1);
        atomicAdd(&g_deg[d.z], 1);
        atomicAdd(&g_deg[d.w], 1);
    } else {
        for (int e = base; e < E_EDGES; e++) atomicAdd(&g_deg[dst[e]], 1);
    }
}

// ---------------- 3) single-pass scan (49 blocks, all resident) --------------
// Also re-zeros g_deg and self-resets flags for the next graph replay.
__global__ __launch_bounds__(SCAN_BLK) void scan_kernel()
{
    __shared__ int warp_sums[32];
    __shared__ int sh_agg[NUM_SCAN_BLOCKS];
    __shared__ int sh_pre;
    const int tid = threadIdx.x, lane = tid & 31, wid = tid >> 5;
    const int bid = blockIdx.x;
    const int i = bid * SCAN_BLK + tid;

    int v = (i < N_NODES) ? g_deg[i] : 0;
    int x = v;
#pragma unroll
    for (int o = 1; o < 32; o <<= 1) {
        int y = __shfl_up_sync(0xffffffffu, x, o);
        if (lane >= o) x += y;
    }
    if (lane == 31) warp_sums[wid] = x;
    __syncthreads();
    if (wid == 0) {
        int s = warp_sums[lane];
#pragma unroll
        for (int o = 1; o < 32; o <<= 1) {
            int y = __shfl_up_sync(0xffffffffu, s, o);
            if (lane >= o) s += y;
        }
        warp_sums[lane] = s;
    }
    __syncthreads();
    int warp_off = (wid > 0) ? warp_sums[wid - 1] : 0;
    int incl = x + warp_off;                 // inclusive within block
    int block_total = warp_sums[31];

    // publish aggregate (+1 so nonzero), poll all blocks
    if (tid == 0) atomicExch((int*)&g_flag[bid], block_total + 1);
    if (tid < NUM_SCAN_BLOCKS) {
        int f;
        do { f = g_flag[tid]; } while (f == 0);
        sh_agg[tid] = f - 1;
    }
    __syncthreads();
    if (tid == 0) {
        int p = 0;
        for (int b = 0; b < bid; b++) p += sh_agg[b];
        sh_pre = p;
        if (bid == NUM_SCAN_BLOCKS - 1) g_off[N_NODES] = p + sh_agg[bid];
    }
    __syncthreads();
    int bpre = sh_pre;
    if (i < N_NODES) {
        int o = bpre + incl - v;
        g_off[i] = o;
        g_cur[i] = o;
        g_deg[i] = 0;                        // restore invariant for next replay
    }
    __syncthreads();                         // whole block done with flags
    if (tid == 0) {
        int d = atomicAdd(&g_done, 1);
        if (d == NUM_SCAN_BLOCKS - 1) {      // last block cleans up
            for (int b = 0; b < NUM_SCAN_BLOCKS; b++) g_flag[b] = 0;
            __threadfence();
            g_done = 0;
        }
    }
}

// ---------------- 4) scatter: CSR payload + w = exp(e2) ----------------------
__global__ void scatter_kernel(const int* __restrict__ src,
                               const int* __restrict__ dst,
                               const float* __restrict__ ppmi)
{
    int e = blockIdx.x * blockDim.x + threadIdx.x;
    if (e >= E_EDGES) return;
    int s = src[e], d = dst[e];
    int pos = atomicAdd(&g_cur[d], 1);
    g_ssrc[pos] = s;
    float lp = logf(ppmi[e]);
    float scale = fmaxf(1.f, logf(fmaxf(1.f, lp)));
    float4 zs = *reinterpret_cast<const float4*>(&g_zsrc[s * NH]);
    float4 zd = *reinterpret_cast<const float4*>(&g_zdst[d * NH]);
    float4 w;
    float t;
    t = zs.x + zd.x; w.x = __expf((t > 0.f ? t : NEG_SLOPE * t) * scale);
    t = zs.y + zd.y; w.y = __expf((t > 0.f ? t : NEG_SLOPE * t) * scale);
    t = zs.z + zd.z; w.z = __expf((t > 0.f ? t : NEG_SLOPE * t) * scale);
    t = zs.w + zd.w; w.w = __expf((t > 0.f ? t : NEG_SLOPE * t) * scale);
    g_w[pos] = w;
}

// ---------------- 5) aggregate: per-dst weighted mean ------------------------
__global__ __launch_bounds__(128) void aggregate_kernel(float* __restrict__ rst)
{
    int n = blockIdx.x;
    int t = threadIdx.x;
    int h = t >> 5;
    int beg = g_off[n], end = g_off[n + 1];
    int cnt = end - beg;

    if (cnt == 0) { rst[n * HD + t] = 0.f; return; }

    const float* wbase = reinterpret_cast<const float*>(g_w);
    float acc = 0.f, wsum = 0.f;
#pragma unroll 4
    for (int i = 0; i < cnt; i++) {
        int s = __ldg(&g_ssrc[beg + i]);
        float w = __ldg(&wbase[(beg + i) * 4 + h]);
        wsum += w;
        acc = fmaf(w, __half2float(g_fth[s * HD + t]), acc);
    }
    rst[n * HD + t] = acc / wsum;
}

// ---------------- launch ------------------------------------------------------
extern "C" void kernel_launch(void* const* d_in, const int* in_sizes, int n_in,
                              void* d_out, int out_size)
{
    const float* feat    = (const float*)d_in[0];
    const int*   src     = (const int*)  d_in[1];
    const int*   dst     = (const int*)  d_in[2];
    const float* ppmi    = (const float*)d_in[3];
    const float* eps_src = (const float*)d_in[4];
    const float* eps_dst = (const float*)d_in[5];
    const float* W       = (const float*)d_in[6];
    const float* mu_src  = (const float*)d_in[7];
    const float* mu_dst  = (const float*)d_in[8];
    const float* lam_src = (const float*)d_in[9];

    float* out     = (float*)d_out;
    float* out_rst = out;
    float* out_mu  = out + N_NODES * HD;
    float* out_lam = out + N_NODES * HD + N_NODES * NH;

    prep_w_kernel<<<(IN_DIM * BN_EXT + 255) / 256, 256>>>(W, mu_src, mu_dst, lam_src);

    cudaFuncSetAttribute(gemm_wmma_kernel,
                         cudaFuncAttributeMaxDynamicSharedMemorySize, GEMM_SMEM_BYTES);
    gemm_wmma_kernel<<<GEMM_BLOCKS, 256, GEMM_SMEM_BYTES>>>(feat, eps_src, eps_dst,
                                                            out_mu, out_lam);

    count_kernel<<<((E_EDGES / 4) + 255) / 256, 256>>>(dst);
    scan_kernel<<<NUM_SCAN_BLOCKS, SCAN_BLK>>>();
    scatter_kernel<<<(E_EDGES + 255) / 256, 256>>>(src, dst, ppmi);
    aggregate_kernel<<<N_NODES, 128>>>(out_rst);
}